// round 4
// baseline (speedup 1.0000x reference)
#include <cuda_runtime.h>
#include <cstddef>

// LoG = GaussianBlur(3,sigma=1) -> Laplacian(ksize=9) + 1, clip [0,255].
// Fused: composite 11x11 = A(x)B(y) + B(x)A(y), A = g3*S9, B = g3*D2_9.
// Reflect-101 pad of 5 on input == staged reflect pads (symmetric kernels).

#define Hn 512
#define Wn 512
#define ROWF 1536            // floats per image row (512*3)
#define TH 32
#define TWP 32
#define HALO 5
#define IN_H 42
#define IN_WP 42
#define IN_PITCH 42          // 42 % 8 == 2 -> conflict-free float2 window reads
#define IN_PLANE 1764        // 42*42
#define HPP 68               // (A,B)-interleaved row pitch; 68 % 32 == 4
#define HAB_PLANE 2860       // 42*68=2856 +4 pad; 2860 % 32 == 12
#define NTHREADS 512

__device__ __forceinline__ int reflect101(int i, int n) {
    i = (i < 0) ? -i : i;
    return (i >= n) ? (2 * n - 2 - i) : i;
}

__global__ __launch_bounds__(NTHREADS, 3)
void log_fused_kernel(const float* __restrict__ x, float* __restrict__ out) {
    extern __shared__ float smem[];
    float* in_s  = smem;                       // 3 planes [IN_H][IN_PITCH]
    float* hAB_s = smem + 3 * IN_PLANE;        // 3 planes [IN_H][HPP], (A,B) pairs

    const float cA[11] = {
        0.274068619061f,  2.644411714f, 11.562892048f, 30.192548953f,
        52.163039333f,   62.326078667f, 52.163039333f, 30.192548953f,
        11.562892048f,    2.644411714f,  0.274068619061f };
    const float cB[11] = {
        0.274068619061f,  1.548137238f,  3.177794143f,  1.807451048f,
       -3.451862762f,    -6.711176571f, -3.451862762f,  1.807451048f,
        3.177794143f,     1.548137238f,  0.274068619061f };

    const int tid = threadIdx.x;
    const int h0  = blockIdx.y * TH;
    const int p0  = blockIdx.x * TWP;
    const size_t plane = (size_t)blockIdx.z * (size_t)(Hn * ROWF);
    const float* xp = x + plane;

    // ================= Phase 1: gmem -> smem (deinterleave, reflect-101) ======
    if (p0 != 0 && p0 != (Wn - TWP)) {
        // interior-W fast path: float4 loads, no column reflect math
        const int fidx0 = (p0 - HALO) * 3 - 1;       // 16B-aligned start
        const int col4  = tid & 31;
        int r = tid >> 5;                            // 0..15

        int qq[4], cc[4];
        bool val[4];
        #pragma unroll
        for (int l = 0; l < 4; l++) {
            int off = 4 * col4 + l - 1;
            val[l] = (off >= 0) && (off < IN_WP * 3);
            int o = val[l] ? off : 0;
            qq[l] = o / 3;
            cc[l] = o - 3 * qq[l];
        }
        const float4* gp = (const float4*)(xp + fidx0 + 4 * col4);

        #pragma unroll
        for (int k = 0; k < 3; k++) {
            if (r < IN_H) {
                const int gh = reflect101(h0 - HALO + r, Hn);
                float4 v = gp[gh * (ROWF / 4)];
                float vv[4] = {v.x, v.y, v.z, v.w};
                const int rb = r * IN_PITCH;
                #pragma unroll
                for (int l = 0; l < 4; l++) {
                    if (val[l]) in_s[cc[l] * IN_PLANE + rb + qq[l]] = vv[l];
                }
            }
            r += 16;
        }
    } else {
        // border-W scalar path (reflect both dims)
        const int f  = tid & 127;
        const int rg = tid >> 7;                     // 0..3
        if (f < IN_WP * 3) {
            const int q = f / 3;
            const int c = f - q * 3;
            const int wp = reflect101(p0 - HALO + q, Wn);
            const int src_col = wp * 3 + c;
            float* dst = in_s + c * IN_PLANE + q;
            #pragma unroll 4
            for (int r = rg; r < IN_H; r += 4) {
                const int gh = reflect101(h0 - HALO + r, Hn);
                dst[r * IN_PITCH] = xp[(size_t)gh * ROWF + src_col];
            }
        }
    }
    __syncthreads();

    // ========== Phase 2: horizontal 11-tap (A and B) =========================
    // r-fast lane mapping: rem = r_lo | (seg<<2) | (r_hi<<4).
    // Reads: 9x LDS.64 (pitch 42 tiles banks perfectly). Stores: 4x STS.128,
    // granules {4*r_lo + 16*seg} -> conflict-free with HPP%32==4.
    if (tid < 504) {
        const int c   = tid / 168;
        const int rem = tid - c * 168;
        int r   = (rem & 3) + ((rem >> 4) << 2);
        int seg = (rem >> 2) & 3;
        if (r >= 42) { r -= 2; seg += 2; }           // remap spill lanes
        const int p = seg << 3;
        const float2* src = (const float2*)(in_s + c * IN_PLANE + r * IN_PITCH + p);

        float aA[8], aB[8];
        #pragma unroll
        for (int j = 0; j < 8; j++) { aA[j] = 0.f; aB[j] = 0.f; }

        #pragma unroll
        for (int w = 0; w < 9; w++) {
            float2 v2 = src[w];
            float vs[2] = {v2.x, v2.y};
            #pragma unroll
            for (int s = 0; s < 2; s++) {
                const int i = 2 * w + s;
                const float v = vs[s];
                #pragma unroll
                for (int j = 0; j < 8; j++) {
                    const int t = i - j;
                    if (t >= 0 && t < 11) {
                        aA[j] = fmaf(cA[t], v, aA[j]);
                        aB[j] = fmaf(cB[t], v, aB[j]);
                    }
                }
            }
        }

        float4* d = (float4*)(hAB_s + c * HAB_PLANE + r * HPP + 2 * p);
        d[0] = make_float4(aA[0], aB[0], aA[1], aB[1]);
        d[1] = make_float4(aA[2], aB[2], aA[3], aB[3]);
        d[2] = make_float4(aA[4], aB[4], aA[5], aB[5]);
        d[3] = make_float4(aA[6], aB[6], aA[7], aB[7]);
    }
    __syncthreads();

    // ========== Phase 3: vertical 11-tap combine, pixel-pair LDS.128 ========
    // 48 column-pair tasks (16 pairs x 3 ch) x 8 four-row chunks = 384 tasks.
    // Lane order q%3=c, q/3=pp with PLANE%32==12 -> all LDS.128 phases are
    // exact bank permutations (conflict-free).
    if (tid < 384) {
        const int q     = tid % 48;
        const int chunk = tid / 48;
        const int c  = q % 3;
        const int pp = q / 3;                        // pixel pair index
        const int r0 = chunk * 4;
        const float4* s = (const float4*)(hAB_s + c * HAB_PLANE + r0 * HPP + 4 * pp);

        float acc0[4], acc1[4];
        #pragma unroll
        for (int j = 0; j < 4; j++) { acc0[j] = 1.0f; acc1[j] = 1.0f; }

        #pragma unroll
        for (int i = 0; i < 14; i++) {
            float4 v = s[i * (HPP / 4)];             // (A0,B0,A1,B1)
            #pragma unroll
            for (int j = 0; j < 4; j++) {
                const int t = i - j;
                if (t >= 0 && t < 11) {
                    acc0[j] = fmaf(cB[t], v.x, acc0[j]);
                    acc0[j] = fmaf(cA[t], v.y, acc0[j]);
                    acc1[j] = fmaf(cB[t], v.z, acc1[j]);
                    acc1[j] = fmaf(cA[t], v.w, acc1[j]);
                }
            }
        }
        float* op = out + plane + (size_t)(h0 + r0) * ROWF + (p0 + 2 * pp) * 3 + c;
        #pragma unroll
        for (int j = 0; j < 4; j++) {
            op[j * ROWF]     = fminf(fmaxf(acc0[j], 0.0f), 255.0f);
            op[j * ROWF + 3] = fminf(fmaxf(acc1[j], 0.0f), 255.0f);
        }
    }
}

extern "C" void kernel_launch(void* const* d_in, const int* in_sizes, int n_in,
                              void* d_out, int out_size) {
    const float* x = (const float*)d_in[0];
    float* out = (float*)d_out;
    const int N = in_sizes[0] / (Hn * Wn * 3);

    const int smem_bytes = (3 * IN_PLANE + 3 * HAB_PLANE) * (int)sizeof(float);
    cudaFuncSetAttribute(log_fused_kernel,
                         cudaFuncAttributeMaxDynamicSharedMemorySize, smem_bytes);

    dim3 grid(Wn / TWP, Hn / TH, N);   // (16, 16, N)
    log_fused_kernel<<<grid, NTHREADS, smem_bytes>>>(x, out);
}